// round 2
// baseline (speedup 1.0000x reference)
#include <cuda_runtime.h>

#define BB  16
#define LL  128
#define LRR 128
#define VV  32000

// Scratch (no allocations allowed anywhere)
__device__ float    g_probs[BB * LL * LRR];   // [b][j][i]  — probs[b,0,i,j] in ref notation
__device__ int      g_hard[BB * LL];          // argmax per (b,j)
__device__ float    g_partial[BB];            // per-batch weighted prob sum
__device__ unsigned g_count = 0;              // last-block counter (self-resetting)

// exp(x) on the FMA pipe: 2^(x*log2e) via magic-number round + degree-4 poly.
// Valid for |x| < ~80; logits are ~N(0,1). Rel err ~3e-5.
__device__ __forceinline__ float fast_exp(float x) {
    float z  = x * 1.4426950408889634f;          // x * log2(e)
    float zf = z + 12582912.0f;                  // round-to-nearest into mantissa (1.5*2^23)
    int   n  = __float_as_int(zf);               // low bits hold round(z) (two's-complement)
    float r  = z - (zf - 12582912.0f);           // r in [-0.5, 0.5]
    float p  = __fmaf_rn(r, 0.0096181291f, 0.0555041086f);
    p        = __fmaf_rn(r, p, 0.2402265069f);
    p        = __fmaf_rn(r, p, 0.6931471806f);
    p        = __fmaf_rn(r, p, 1.0f);
    return p * __int_as_float((n << 23) + 0x3F800000);
}

// Labels-dtype detect, inlined per block: int64 LE => every odd 32-bit word is a
// zero high half. P(false positive with int32 in [0,32000)) ~ (1/2^17)^32 ~ 0.
// Warp-0 collective; result to shared.
__device__ __forceinline__ void detect_is64(const int* __restrict__ lab_raw,
                                            int t, int* s_is64) {
    if (t < 32) {
        int ok  = (lab_raw[2 * t + 1] == 0);
        int all = __all_sync(0xffffffffu, ok);
        if (t == 0) *s_is64 = all;
    }
}

// One block per (b,j): streaming reduce of 32000 logits -> (sumexp, argmax),
// then gather 128 label probs (L1/L2 hits — row just streamed).
__global__ __launch_bounds__(256) void k1(const float* __restrict__ logits,
                                          const int* __restrict__ lab_raw) {
    const int row  = blockIdx.x;          // b*LL + j
    const int b    = row >> 7;
    const int t    = threadIdx.x;
    const int w    = t >> 5, lane = t & 31;
    const float* __restrict__ base = logits + (size_t)row * VV;

    __shared__ float s_s[8];
    __shared__ float s_v[8];
    __shared__ int   s_i[8];
    __shared__ int   s_lab[LRR];
    __shared__ float s_inv;
    __shared__ int   s_is64;

    detect_is64(lab_raw, t, &s_is64);
    __syncthreads();
    if (t < LRR) {
        s_lab[t] = s_is64 ? lab_raw[(b * LRR + t) * 2] : lab_raw[b * LRR + t];
    }

    float acc0 = 0.0f, acc1 = 0.0f;
    float vmax = -3.0e38f;
    int   imax = 0;
    const float4* b4 = (const float4*)base;
    #pragma unroll 4
    for (int k = t; k < VV / 4; k += 256) {
        float4 v = __ldg(&b4[k]);
        acc0 += fast_exp(v.x) + fast_exp(v.y);
        acc1 += fast_exp(v.z) + fast_exp(v.w);
        // fmax tree: no dependence on vmax -> no serial predicate chain
        float m = fmaxf(fmaxf(v.x, v.y), fmaxf(v.z, v.w));
        if (m > vmax) {              // rarely taken (~H(31)≈4 times/thread)
            vmax = m;
            int i0 = k << 2;
            imax = (v.x == m) ? i0 : (v.y == m) ? i0 + 1 : (v.z == m) ? i0 + 2 : i0 + 3;
        }
    }
    float acc = acc0 + acc1;

    // warp reduce: sum + (max, first-index) — tie -> smaller global index
    #pragma unroll
    for (int off = 16; off; off >>= 1) {
        acc += __shfl_down_sync(0xffffffffu, acc, off);
        float ov = __shfl_down_sync(0xffffffffu, vmax, off);
        int   oi = __shfl_down_sync(0xffffffffu, imax, off);
        if (ov > vmax || (ov == vmax && oi < imax)) { vmax = ov; imax = oi; }
    }
    if (lane == 0) { s_s[w] = acc; s_v[w] = vmax; s_i[w] = imax; }
    __syncthreads();
    if (t == 0) {
        float ts = s_s[0], tv = s_v[0];
        int   ti = s_i[0];
        #pragma unroll
        for (int q = 1; q < 8; q++) {
            ts += s_s[q];
            if (s_v[q] > tv || (s_v[q] == tv && s_i[q] < ti)) { tv = s_v[q]; ti = s_i[q]; }
        }
        s_inv = 1.0f / ts;
        g_hard[row] = ti;
    }
    __syncthreads();
    if (t < LRR) {
        // probs[b,0,i=t,j] = exp(logit[label]) / sumexp ; coalesced store [b][j][i]
        g_probs[row * LRR + t] = fast_exp(__ldg(&base[s_lab[t]])) * s_inv;
    }
}

// One block per batch: sudoku (greedy 1-1 match) + weighted prob sum.
// Final overlap weights: 1.0 selected, 0.5 both-unmatched, 0.1 otherwise:
//   cell sum = 0.1*S_all + 0.4*S_both_unmatched + 0.9*S_selected
// Last block finishes: loss = 1 - (sum_b total_b) / 2048  (Lr+L-1+1 = 256; *2 /256 /16)
__global__ __launch_bounds__(128) void k2(const int* __restrict__ lab_raw,
                                          float* __restrict__ out) {
    const int b = blockIdx.x;
    const int i = threadIdx.x;

    __shared__ int           s_hard[LL];
    __shared__ int           s_fj[LRR];
    __shared__ unsigned char s_col[LL];
    __shared__ float         s_red[LRR];
    __shared__ int           s_is64;
    __shared__ unsigned      s_ticket;

    detect_is64(lab_raw, i, &s_is64);
    s_hard[i] = g_hard[b * LL + i];
    s_col[i]  = 0;
    __syncthreads();
    int lab = s_is64 ? lab_raw[(b * LRR + i) * 2] : lab_raw[b * LRR + i];

    // row_first: first j with hard[j] == label[i]
    int fj = -1;
    for (int j = 0; j < LL; j++) {
        if (s_hard[j] == lab) { fj = j; break; }
    }
    s_fj[i] = fj;
    __syncthreads();

    // column dedup: keep only the smallest i claiming column fj
    int sel = 0;
    if (fj >= 0) {
        sel = 1;
        for (int ip = 0; ip < i; ip++) {
            if (s_fj[ip] == fj) { sel = 0; break; }
        }
    }
    if (sel) s_col[fj] = 1;   // column j is matched
    __syncthreads();

    const float* pb = g_probs + b * LL * LRR;
    float sum_all = 0.0f, sum_unm = 0.0f;
    for (int j = 0; j < LL; j++) {
        float p = pb[j * LRR + i];           // coalesced across i
        sum_all += p;
        if (!s_col[j]) sum_unm += p;
    }
    float c = 0.1f * sum_all;
    if (sel) c += 0.9f * pb[fj * LRR + i];   // selected cell (row matched)
    else     c += 0.4f * sum_unm;            // row unmatched: both-unmatched cells

    s_red[i] = c;
    __syncthreads();
    #pragma unroll
    for (int off = 64; off > 0; off >>= 1) {
        if (i < off) s_red[i] += s_red[i + off];
        __syncthreads();
    }
    if (i == 0) {
        g_partial[b] = s_red[0];
        __threadfence();                       // partial visible before ticket
        s_ticket = atomicAdd(&g_count, 1u);
    }
    __syncthreads();

    // Last block to arrive finalizes (deterministic: fixed-order sum of g_partial)
    if (s_ticket == BB - 1 && i == 0) {
        float s = 0.0f;
        #pragma unroll
        for (int q = 0; q < BB; q++) s += g_partial[q];
        out[0] = 1.0f - s * (1.0f / 2048.0f);
        g_count = 0;                           // reset for next graph replay
    }
}

extern "C" void kernel_launch(void* const* d_in, const int* in_sizes, int n_in,
                              void* d_out, int out_size) {
    // Resolve input order by element count (logits: 65.5M; labels: 2048 or 4096 words)
    int li = (in_sizes[0] > in_sizes[1]) ? 0 : 1;
    const float* logits = (const float*)d_in[li];
    const int*   labels = (const int*)d_in[1 - li];

    k1<<<BB * LL, 256>>>(logits, labels);
    k2<<<BB, 128>>>(labels, (float*)d_out);
}

// round 3
// speedup vs baseline: 1.2869x; 1.2869x over previous
#include <cuda_runtime.h>

#define BB  16
#define LL  128
#define LRR 128
#define VV  32000

// Scratch (no allocations allowed anywhere)
__device__ float    g_probs[BB * LL * LRR];   // [b][j][i]  — probs[b,0,i,j] in ref notation
__device__ int      g_hard[BB * LL];          // argmax per (b,j)
__device__ float    g_partial[BB];            // per-batch weighted prob sum
__device__ unsigned g_count = 0;              // last-block counter (self-resetting)

// exp(x) on the FMA pipe: 2^(x*log2e) via magic-number round + degree-4 poly.
// Valid for |x| < ~80; logits are ~N(0,1). Rel err ~3e-5.
__device__ __forceinline__ float fast_exp(float x) {
    float z  = x * 1.4426950408889634f;          // x * log2(e)
    float zf = z + 12582912.0f;                  // round-to-nearest into mantissa
    int   n  = __float_as_int(zf);
    float r  = z - (zf - 12582912.0f);           // r in [-0.5, 0.5]
    float p  = __fmaf_rn(r, 0.0096181291f, 0.0555041086f);
    p        = __fmaf_rn(r, p, 0.2402265069f);
    p        = __fmaf_rn(r, p, 0.6931471806f);
    p        = __fmaf_rn(r, p, 1.0f);
    return p * __int_as_float((n << 23) + 0x3F800000);
}

// Labels-dtype detect: int64 LE => every odd 32-bit word is a zero high half.
// Warp-0 collective; result to shared.
__device__ __forceinline__ void detect_is64(const int* __restrict__ lab_raw,
                                            int t, int* s_is64) {
    if (t < 32) {
        int ok  = (lab_raw[2 * t + 1] == 0);
        int all = __all_sync(0xffffffffu, ok);
        if (t == 0) *s_is64 = all;
    }
}

// One block per (b,j): streaming reduce of 32000 logits -> (sumexp, argmax),
// then gather 128 label probs (L1/L2 hits — row just streamed).
// Hot loop is STRAIGHT-LINE (predicated only) so ptxas front-batches the loads.
__global__ __launch_bounds__(256) void k1(const float* __restrict__ logits,
                                          const int* __restrict__ lab_raw) {
    const int row  = blockIdx.x;          // b*LL + j
    const int b    = row >> 7;
    const int t    = threadIdx.x;
    const int w    = t >> 5, lane = t & 31;
    const float* __restrict__ base = logits + (size_t)row * VV;

    __shared__ float s_s[8];
    __shared__ float s_v[8];
    __shared__ int   s_i[8];
    __shared__ int   s_lab[LRR];
    __shared__ float s_inv;
    __shared__ int   s_is64;

    detect_is64(lab_raw, t, &s_is64);
    __syncthreads();
    if (t < LRR) {
        s_lab[t] = s_is64 ? lab_raw[(b * LRR + t) * 2] : lab_raw[b * LRR + t];
    }

    float acc0 = 0.0f, acc1 = 0.0f;
    float vmax  = -3.0e38f;
    int   kbest = t;                       // winning quad index (exact elem found later)
    const float4* b4 = (const float4*)base;
    #pragma unroll 4
    for (int k = t; k < VV / 4; k += 256) {
        float4 v = __ldg(&b4[k]);
        acc0 += fast_exp(v.x) + fast_exp(v.y);
        acc1 += fast_exp(v.z) + fast_exp(v.w);
        float m = fmaxf(fmaxf(v.x, v.y), fmaxf(v.z, v.w));
        bool upd = m > vmax;               // strict > keeps earliest quad (first occurrence)
        kbest = upd ? k : kbest;
        vmax  = upd ? m : vmax;
    }
    float acc = acc0 + acc1;

    // Reconstruct exact element index once (quad reload hits L1)
    int imax;
    {
        float4 v = __ldg(&b4[kbest]);
        int i0 = kbest << 2;
        imax = (v.x == vmax) ? i0 : (v.y == vmax) ? i0 + 1
             : (v.z == vmax) ? i0 + 2 : i0 + 3;
    }

    // warp reduce: sum + (max, first-index) — tie -> smaller global index
    #pragma unroll
    for (int off = 16; off; off >>= 1) {
        acc += __shfl_down_sync(0xffffffffu, acc, off);
        float ov = __shfl_down_sync(0xffffffffu, vmax, off);
        int   oi = __shfl_down_sync(0xffffffffu, imax, off);
        if (ov > vmax || (ov == vmax && oi < imax)) { vmax = ov; imax = oi; }
    }
    if (lane == 0) { s_s[w] = acc; s_v[w] = vmax; s_i[w] = imax; }
    __syncthreads();
    if (t == 0) {
        float ts = s_s[0], tv = s_v[0];
        int   ti = s_i[0];
        #pragma unroll
        for (int q = 1; q < 8; q++) {
            ts += s_s[q];
            if (s_v[q] > tv || (s_v[q] == tv && s_i[q] < ti)) { tv = s_v[q]; ti = s_i[q]; }
        }
        s_inv = 1.0f / ts;
        g_hard[row] = ti;
    }
    __syncthreads();
    if (t < LRR) {
        // probs[b,0,i=t,j] = exp(logit[label]) / sumexp ; coalesced store [b][j][i]
        g_probs[row * LRR + t] = fast_exp(__ldg(&base[s_lab[t]])) * s_inv;
    }
}

// One block per batch, 1024 threads.
// Phase A (threads 0..127): sudoku greedy 1-1 match -> s_fj, s_sel, s_col.
// Phase B (all 1024): weighted prob sum. Weights: 1.0 selected cell,
//   0.5 both-row-and-col unmatched, 0.1 otherwise (clip floor).
// Last block finalizes: loss = 1 - (sum_b total_b) / 2048.
__global__ __launch_bounds__(1024) void k2(const int* __restrict__ lab_raw,
                                           float* __restrict__ out) {
    const int b = blockIdx.x;
    const int t = threadIdx.x;

    __shared__ int           s_hard[LL];
    __shared__ int           s_fj[LRR];
    __shared__ unsigned char s_col[LL];
    __shared__ unsigned char s_sel[LRR];
    __shared__ float         s_red[32];
    __shared__ int           s_is64;
    __shared__ unsigned      s_ticket;

    detect_is64(lab_raw, t, &s_is64);
    if (t < LL) { s_hard[t] = g_hard[b * LL + t]; s_col[t] = 0; }
    __syncthreads();

    if (t < LRR) {
        int lab = s_is64 ? lab_raw[(b * LRR + t) * 2] : lab_raw[b * LRR + t];
        // row_first: first j with hard[j] == label[i=t]
        int fj = -1;
        for (int j = 0; j < LL; j++) {
            if (s_hard[j] == lab) { fj = j; break; }
        }
        s_fj[t] = fj;
    }
    __syncthreads();

    if (t < LRR) {
        // column dedup: keep only the smallest i claiming column fj
        int fj = s_fj[t];
        int sel = 0;
        if (fj >= 0) {
            sel = 1;
            for (int ip = 0; ip < t; ip++) {
                if (s_fj[ip] == fj) { sel = 0; break; }
            }
        }
        s_sel[t] = (unsigned char)sel;
        if (sel) s_col[fj] = 1;            // column j matched
    }
    __syncthreads();

    // Phase B: all 1024 threads, 16 cells each (coalesced; independent loads)
    const float* __restrict__ pb = g_probs + b * LL * LRR;   // [j][i]
    float acc = 0.0f;
    #pragma unroll
    for (int idx = 0; idx < LL * LRR; idx += 1024) {
        int cell = idx + t;
        int j = cell >> 7, i = cell & 127;
        float p = pb[cell];
        float w = 0.1f;
        if (s_sel[i] && s_fj[i] == j)            w = 1.0f;   // selected match
        else if (!s_sel[i] && !s_col[j])         w = 0.5f;   // both unmatched
        acc += w * p;
    }

    // Block reduce (deterministic order)
    #pragma unroll
    for (int off = 16; off; off >>= 1)
        acc += __shfl_down_sync(0xffffffffu, acc, off);
    if ((t & 31) == 0) s_red[t >> 5] = acc;
    __syncthreads();
    if (t == 0) {
        float s = 0.0f;
        #pragma unroll
        for (int q = 0; q < 32; q++) s += s_red[q];
        g_partial[b] = s;
        __threadfence();                   // partial visible before ticket
        s_ticket = atomicAdd(&g_count, 1u);
        if (s_ticket == BB - 1) {
            float tot = 0.0f;
            #pragma unroll
            for (int q = 0; q < BB; q++) tot += g_partial[q];
            out[0] = 1.0f - tot * (1.0f / 2048.0f);
            g_count = 0;                   // reset for next graph replay
        }
    }
}

extern "C" void kernel_launch(void* const* d_in, const int* in_sizes, int n_in,
                              void* d_out, int out_size) {
    // Resolve input order by element count (logits: 65.5M; labels: 2048/4096 words)
    int li = (in_sizes[0] > in_sizes[1]) ? 0 : 1;
    const float* logits = (const float*)d_in[li];
    const int*   labels = (const int*)d_in[1 - li];

    k1<<<BB * LL, 256>>>(logits, labels);
    k2<<<BB, 1024>>>(labels, (float*)d_out);
}

// round 4
// speedup vs baseline: 1.4817x; 1.1514x over previous
#include <cuda_runtime.h>

#define BB  16
#define LL  128
#define LRR 128
#define VV  32000

// Scratch (no allocations allowed anywhere)
__device__ float    g_probs[BB * LL * LRR];   // [b][j][i]  — probs[b,0,i,j] in ref notation
__device__ int      g_hard[BB * LL];          // argmax per (b,j)
__device__ float    g_partial[BB];            // per-batch weighted prob sum
__device__ unsigned g_count = 0;              // last-block counter (self-resetting)

// Labels-dtype detect: int64 LE => every odd 32-bit word is a zero high half.
__device__ __forceinline__ void detect_is64(const int* __restrict__ lab_raw,
                                            int t, int* s_is64) {
    if (t < 32) {
        int ok  = (lab_raw[2 * t + 1] == 0);
        int all = __all_sync(0xffffffffu, ok);
        if (t == 0) *s_is64 = all;
    }
}

// One block per (b,j): streaming reduce of 32000 logits -> (sumexp, argmax),
// then gather 128 label probs (L1/L2 hits — row just streamed).
// exp via MUFU (__expf): FMA pipe stays light -> loop is memory-bound.
// Hot loop is STRAIGHT-LINE (predicated only) so ptxas front-batches the loads.
__global__ __launch_bounds__(256) void k1(const float* __restrict__ logits,
                                          const int* __restrict__ lab_raw) {
    const int row  = blockIdx.x;          // b*LL + j
    const int b    = row >> 7;
    const int t    = threadIdx.x;
    const int w    = t >> 5, lane = t & 31;
    const float* __restrict__ base = logits + (size_t)row * VV;

    __shared__ float s_s[8];
    __shared__ float s_v[8];
    __shared__ int   s_i[8];
    __shared__ int   s_lab[LRR];
    __shared__ float s_inv;
    __shared__ int   s_is64;

    detect_is64(lab_raw, t, &s_is64);
    __syncthreads();
    if (t < LRR) {
        s_lab[t] = s_is64 ? lab_raw[(b * LRR + t) * 2] : lab_raw[b * LRR + t];
    }

    float acc0 = 0.0f, acc1 = 0.0f;
    float vmax  = -3.0e38f;
    int   kbest = t;                       // winning quad index (exact elem found later)
    const float4* b4 = (const float4*)base;
    #pragma unroll 4
    for (int k = t; k < VV / 4; k += 256) {
        float4 v = __ldg(&b4[k]);
        acc0 += __expf(v.x) + __expf(v.y);   // MUFU.EX2 path
        acc1 += __expf(v.z) + __expf(v.w);
        float m = fmaxf(fmaxf(v.x, v.y), fmaxf(v.z, v.w));
        bool upd = m > vmax;               // strict > keeps earliest quad (first occurrence)
        kbest = upd ? k : kbest;
        vmax  = upd ? m : vmax;
    }
    float acc = acc0 + acc1;

    // Reconstruct exact element index once (quad reload hits L1)
    int imax;
    {
        float4 v = __ldg(&b4[kbest]);
        int i0 = kbest << 2;
        imax = (v.x == vmax) ? i0 : (v.y == vmax) ? i0 + 1
             : (v.z == vmax) ? i0 + 2 : i0 + 3;
    }

    // warp reduce: sum + (max, first-index) — tie -> smaller global index
    #pragma unroll
    for (int off = 16; off; off >>= 1) {
        acc += __shfl_down_sync(0xffffffffu, acc, off);
        float ov = __shfl_down_sync(0xffffffffu, vmax, off);
        int   oi = __shfl_down_sync(0xffffffffu, imax, off);
        if (ov > vmax || (ov == vmax && oi < imax)) { vmax = ov; imax = oi; }
    }
    if (lane == 0) { s_s[w] = acc; s_v[w] = vmax; s_i[w] = imax; }
    __syncthreads();
    if (t == 0) {
        float ts = s_s[0], tv = s_v[0];
        int   ti = s_i[0];
        #pragma unroll
        for (int q = 1; q < 8; q++) {
            ts += s_s[q];
            if (s_v[q] > tv || (s_v[q] == tv && s_i[q] < ti)) { tv = s_v[q]; ti = s_i[q]; }
        }
        s_inv = 1.0f / ts;
        g_hard[row] = ti;
    }
    __syncthreads();
    if (t < LRR) {
        // probs[b,0,i=t,j] = exp(logit[label]) / sumexp ; coalesced store [b][j][i]
        g_probs[row * LRR + t] = __expf(__ldg(&base[s_lab[t]])) * s_inv;
    }
}

// One block per batch, 1024 threads. Sudoku via shared-mem atomicMin (no serial
// scans: labels are ~uniform in [0,32000) so matches are rare and atomics
// almost never contend).
//   s_fj[i]     = min j with hard[j]==label[i]        (row-first match)
//   s_colwin[j] = min i among rows claiming column j  (column dedup winner)
// Weights: 1.0 selected cell; 0.5 when row i unselected AND column j unclaimed;
// 0.1 otherwise (clip floor). Last block finalizes loss = 1 - total/2048.
#define NONE 0x7fffffff
__global__ __launch_bounds__(1024) void k2(const int* __restrict__ lab_raw,
                                           float* __restrict__ out) {
    const int b = blockIdx.x;
    const int t = threadIdx.x;

    __shared__ int           s_hard[LL];
    __shared__ int           s_lab[LRR];
    __shared__ int           s_fj[LRR];
    __shared__ int           s_colwin[LL];
    __shared__ unsigned char s_sel[LRR];
    __shared__ float         s_red[32];
    __shared__ int           s_is64;

    detect_is64(lab_raw, t, &s_is64);
    if (t < LL) {
        s_hard[t]   = g_hard[b * LL + t];
        s_fj[t]     = NONE;
        s_colwin[t] = NONE;
    }
    __syncthreads();
    if (t < LRR) {
        s_lab[t] = s_is64 ? lab_raw[(b * LRR + t) * 2] : lab_raw[b * LRR + t];
    }
    __syncthreads();

    // Row-first: scan all 16384 (i,j) cells, 16 per thread. i fast, j slow:
    // s_lab[i] stride-1 conflict-free, s_hard[j] broadcast.
    #pragma unroll
    for (int c = 0; c < LL * LRR; c += 1024) {
        int cell = c + t;
        int i = cell & 127, j = cell >> 7;
        if (s_hard[j] == s_lab[i]) atomicMin(&s_fj[i], j);
    }
    __syncthreads();

    // Column dedup: winner of column fj[i] is the smallest i
    if (t < LRR) {
        int fj = s_fj[t];
        if (fj != NONE) atomicMin(&s_colwin[fj], t);
    }
    __syncthreads();
    if (t < LRR) {
        int fj = s_fj[t];
        s_sel[t] = (unsigned char)(fj != NONE && s_colwin[fj] == t);
    }
    __syncthreads();

    // Weighted sum over all cells (16 per thread, coalesced over g_probs [j][i])
    const float* __restrict__ pb = g_probs + b * LL * LRR;
    float acc = 0.0f;
    #pragma unroll
    for (int c = 0; c < LL * LRR; c += 1024) {
        int cell = c + t;
        int i = cell & 127, j = cell >> 7;
        float p = pb[cell];
        float wgt = 0.1f;
        if (s_sel[i] && s_fj[i] == j)                      wgt = 1.0f;  // selected
        else if (!s_sel[i] && s_colwin[j] == NONE)         wgt = 0.5f;  // both unmatched
        acc += wgt * p;
    }

    // Block reduce (deterministic order)
    #pragma unroll
    for (int off = 16; off; off >>= 1)
        acc += __shfl_down_sync(0xffffffffu, acc, off);
    if ((t & 31) == 0) s_red[t >> 5] = acc;
    __syncthreads();
    if (t == 0) {
        float s = 0.0f;
        #pragma unroll
        for (int q = 0; q < 32; q++) s += s_red[q];
        g_partial[b] = s;
        __threadfence();                   // partial visible before ticket
        unsigned ticket = atomicAdd(&g_count, 1u);
        if (ticket == BB - 1) {
            float tot = 0.0f;
            #pragma unroll
            for (int q = 0; q < BB; q++) tot += g_partial[q];
            out[0] = 1.0f - tot * (1.0f / 2048.0f);
            g_count = 0;                   // reset for next graph replay
        }
    }
}

extern "C" void kernel_launch(void* const* d_in, const int* in_sizes, int n_in,
                              void* d_out, int out_size) {
    // Resolve input order by element count (logits: 65.5M; labels: 2048/4096 words)
    int li = (in_sizes[0] > in_sizes[1]) ? 0 : 1;
    const float* logits = (const float*)d_in[li];
    const int*   labels = (const int*)d_in[1 - li];

    k1<<<BB * LL, 256>>>(logits, labels);
    k2<<<BB, 1024>>>(labels, (float*)d_out);
}